// round 7
// baseline (speedup 1.0000x reference)
#include <cuda_runtime.h>
#include <cuda_fp16.h>
#include <math.h>
#include <stdint.h>

// ---------------- problem constants ----------------
#define Nn 262144
#define Dd 64
#define Kk 64
#define TMR 256            // rows per tile
#define NT (Nn/TMR)        // 1024 tiles
#define TPB 256
#define GRID 296           // persistent CTAs (2 per SM x 148)
#define LOG2PI_F 1.83787706640934548356f
#define EXP2_F 7.389056098930650f    // exp(2) = exp(-prior_logvar_0)
#define AS 72              // A_s row stride in halves (144B: conflict-free ldmatrix)

// ---------------- device globals ----------------
__device__ double g_lse;
__device__ unsigned int g_count;
__device__ unsigned int g_tile;

// ---------------- smem layout (bytes) ----------------
#define OFF_A    0                   // 256*72*2 = 36864   fp16 X tile
#define OFF_BGP  36864               // 256*4*4  = 4096    fp32 bg partials
#define OFF_B    40960               // 8*4*32*16 = 16384  packed B fragments
#define OFF_OFFS 57344               // 64 f32
#define OFF_LPI  57600               // 64 f32
#define OFF_WBG  57856               // 64 f32
#define OFF_SCR  58112               // 256 f32 scratch
#define SMEM_BYTES 59136

__device__ __forceinline__ void mma16(float c[4], const uint32_t a[4],
                                      uint32_t b0, uint32_t b1) {
    asm volatile("mma.sync.aligned.m16n8k16.row.col.f32.f16.f16.f32 "
        "{%0,%1,%2,%3},{%4,%5,%6,%7},{%8,%9},{%0,%1,%2,%3};"
        : "+f"(c[0]), "+f"(c[1]), "+f"(c[2]), "+f"(c[3])
        : "r"(a[0]), "r"(a[1]), "r"(a[2]), "r"(a[3]), "r"(b0), "r"(b1));
}
#define LDM_X4(A, addr) \
    asm volatile("ldmatrix.sync.aligned.m8n8.x4.shared.b16 {%0,%1,%2,%3}, [%4];" \
        : "=r"((A)[0]), "=r"((A)[1]), "=r"((A)[2]), "=r"((A)[3]) : "r"(addr))

__device__ __forceinline__ uint32_t h2sq(uint32_t a) {
    __half2 h = *reinterpret_cast<__half2*>(&a);
    __half2 q = __hmul2(h, h);
    return *reinterpret_cast<uint32_t*>(&q);
}
__device__ __forceinline__ uint32_t f2h2(float lo, float hi) {
    __half2 h = __floats2half2_rn(lo, hi);
    return *reinterpret_cast<uint32_t*>(&h);
}

// ---------------------------------------------------------------------------
__global__ void __launch_bounds__(TPB, 2)
gmm_kernel(const float* __restrict__ X,
           const float* __restrict__ u_noise,
           const float* __restrict__ phi_logits,
           const float* __restrict__ q_mu,
           const float* __restrict__ q_logvar,
           const float* __restrict__ pi_logits,
           const float* __restrict__ prior_p,
           float* __restrict__ out)
{
    extern __shared__ char smraw[];
    __half* A_s    = (__half*)(smraw + OFF_A);
    float*  bgp_s  = (float*) (smraw + OFF_BGP);
    float4* B_s    = (float4*)(smraw + OFF_B);
    float*  offs_s = (float*) (smraw + OFF_OFFS);
    float*  lpi_s  = (float*) (smraw + OFF_LPI);
    float*  wbg_s  = (float*) (smraw + OFF_WBG);
    float*  scr    = (float*) (smraw + OFF_SCR);

    __shared__ float phi_s[64];
    __shared__ float kl_s, c0_s;
    __shared__ unsigned int s_tile;
    __shared__ double wsum[TPB / 32];

    const int tid = threadIdx.x, wid = tid >> 5, lane = tid & 31;
    const int g = lane >> 2, t4 = lane & 3;

    // ---------------- in-CTA precompute ----------------
    if (tid < 64) {
        float uu  = u_noise[tid];
        float gmb = -__logf(-__logf(uu + 1e-9f) + 1e-9f);
        float pl  = phi_logits[tid];
        float phi = 1.0f / (1.0f + __expf(-(pl + gmb)));
        phi_s[tid] = phi;
        float qphi = 1.0f / (1.0f + __expf(-pl));
        qphi = fminf(fmaxf(qphi, 1e-6f), 1.0f - 1e-6f);
        if (blockIdx.x == 0) out[1 + tid] = qphi;
        float p = fminf(fmaxf(prior_p[tid], 1e-6f), 1.0f - 1e-6f);
        scr[tid]       = qphi * (__logf(qphi) - __logf(p))
                       + (1.0f - qphi) * (__logf(1.0f - qphi) - __logf(1.0f - p));
        scr[64 + tid]  = (1.0f - phi) * (LOG2PI_F - 2.0f);
        scr[128 + tid] = pi_logits[tid];
        wbg_s[tid]     = (1.0f - phi) * EXP2_F;
    }
    __syncthreads();
    if (tid == 0) {
        float kl = 0.f, c0 = 0.f;
        #pragma unroll
        for (int i = 0; i < 64; i++) { kl += scr[i]; c0 += scr[64 + i]; }
        kl_s = kl; c0_s = c0;
    }
    if (tid < 64) {     // log(softmax(pi)+1e-9), broadcast smem reads
        float m = -3.4e38f;
        #pragma unroll
        for (int k = 0; k < 64; k++) m = fmaxf(m, scr[128 + k]);
        float ss = 0.f;
        #pragma unroll
        for (int k = 0; k < 64; k++) ss += __expf(scr[128 + k] - m);
        lpi_s[tid] = __logf(__expf(scr[128 + tid] - m) / ss + 1e-9f);
    }

    // packed B fragments: entry e = (j*4 + ks)*32 + lane_e
    // float4 = { h2(lin d0,d0+1), h2(lin d0+8,d0+9), h2(a d0,d0+1), h2(a d0+8,d0+9) }
    for (int e = tid; e < 8 * 4 * 32; e += TPB) {
        int le = e & 31, ks = (e >> 5) & 3, j = e >> 7;
        int n = 8 * j + (le >> 2);
        int d0 = 16 * ks + 2 * (le & 3);
        float lin[4], aa[4];
        #pragma unroll
        for (int p = 0; p < 4; p++) {
            int d = d0 + (p & 1) + (p >> 1) * 8;       // d0, d0+1, d0+8, d0+9
            float lv = fminf(fmaxf(q_logvar[n * Dd + d], -5.0f), 5.0f);
            float a  = phi_s[d] * __expf(-lv);
            aa[p]  = a;
            lin[p] = -2.0f * q_mu[n * Dd + d] * a;
        }
        float4 v;
        *(uint32_t*)&v.x = f2h2(lin[0], lin[1]);
        *(uint32_t*)&v.y = f2h2(lin[2], lin[3]);
        *(uint32_t*)&v.z = f2h2(aa[0],  aa[1]);
        *(uint32_t*)&v.w = f2h2(aa[2],  aa[3]);
        B_s[e] = v;
    }
    __syncthreads();    // scr consumers done; reuse scr for offs partials
    {
        int k = tid & 63, part = tid >> 6;
        float s = 0.f;
        #pragma unroll
        for (int d = part * 16; d < part * 16 + 16; d++) {
            float lv = fminf(fmaxf(q_logvar[k * Dd + d], -5.0f), 5.0f);
            float a  = phi_s[d] * __expf(-lv);
            float mu = q_mu[k * Dd + d];
            s += phi_s[d] * (LOG2PI_F + lv) + mu * mu * a;
        }
        scr[tid] = s;
    }
    __syncthreads();
    if (tid < 64)
        offs_s[tid] = -0.5f * (scr[tid] + scr[64 + tid] + scr[128 + tid] + scr[192 + tid]);

    // per-lane ldmatrix base addresses (two m16 tiles per warp)
    uint32_t a_sh = (uint32_t)__cvta_generic_to_shared(A_s);
    int rbase = 32 * wid + (lane & 15);
    uint32_t lm0 = a_sh + ((uint32_t)rbase * AS + ((lane >> 4) << 3)) * 2u;
    uint32_t lm1 = lm0 + 16u * AS * 2u;

    const float C0 = c0_s;
    double lsesum = 0.0;

    // =================== work-stealing tile loop ===================
    for (;;) {
        if (tid == 0) s_tile = atomicAdd(&g_tile, 1u);
        __syncthreads();                 // also: everyone done with A_s/bgp_s
        unsigned int tile = s_tile;
        if (tile >= NT) break;
        const float* Xt = X + (size_t)tile * TMR * Dd;

        // ---- stage X -> fp16 smem + exact fp32 bg partials ----
        #pragma unroll
        for (int it = 0; it < 16; it++) {
            int i4 = tid + TPB * it;     // 4096 float4s
            int m = i4 >> 4, q = (i4 & 15) << 2;
            float4 v = *(const float4*)(Xt + m * Dd + q);
            uint2 hv = make_uint2(f2h2(v.x, v.y), f2h2(v.z, v.w));
            *(uint2*)(A_s + m * AS + q) = hv;
            float4 w = *(const float4*)(wbg_s + q);
            float s = v.x*v.x*w.x + v.y*v.y*w.y + v.z*v.z*w.z + v.w*v.w*w.w;
            s += __shfl_xor_sync(0xffffffffu, s, 1);
            s += __shfl_xor_sync(0xffffffffu, s, 2);
            if ((lane & 3) == 0) bgp_s[m * 4 + ((lane & 15) >> 2)] = s;
        }
        __syncthreads();

        // ---- fp16 MMA: 4 k-steps x 8 n-tiles x (lin+quad) x 2 m-tiles ----
        float c[2][8][4];
        #pragma unroll
        for (int u = 0; u < 2; u++)
            #pragma unroll
            for (int j = 0; j < 8; j++)
                { c[u][j][0]=0.f; c[u][j][1]=0.f; c[u][j][2]=0.f; c[u][j][3]=0.f; }

        #pragma unroll
        for (int ks = 0; ks < 4; ks++) {
            uint32_t A0[4], A1[4], Q0[4], Q1[4];
            LDM_X4(A0, lm0 + ks * 32u);
            LDM_X4(A1, lm1 + ks * 32u);
            #pragma unroll
            for (int i = 0; i < 4; i++) { Q0[i] = h2sq(A0[i]); Q1[i] = h2sq(A1[i]); }
            const float4* bp = B_s + ks * 32 + lane;
            #pragma unroll
            for (int j = 0; j < 8; j++) {
                float4 b = bp[j * 128];
                uint32_t bl0 = *(uint32_t*)&b.x, bl1 = *(uint32_t*)&b.y;
                uint32_t bq0 = *(uint32_t*)&b.z, bq1 = *(uint32_t*)&b.w;
                mma16(c[0][j], A0, bl0, bl1);
                mma16(c[0][j], Q0, bq0, bq1);
                mma16(c[1][j], A1, bl0, bl1);
                mma16(c[1][j], Q1, bq0, bq1);
            }
        }

        // ---- epilogue: lp, logsumexp, direct stores ----
        int n0 = tile * TMR;
        #pragma unroll
        for (int u = 0; u < 2; u++) {
            #pragma unroll
            for (int h = 0; h < 2; h++) {
                int r = 32 * wid + 16 * u + 8 * h + g;       // tile-local row
                float4 bp4 = *(float4*)(bgp_s + r * 4);
                float lpbg = -0.5f * (C0 + bp4.x + bp4.y + bp4.z + bp4.w);
                float lp[16];
                float mx = -3.4e38f;
                #pragma unroll
                for (int j = 0; j < 8; j++) {
                    int col = 8 * j + 2 * t4;
                    float v0 = fmaf(-0.5f, c[u][j][2*h],   offs_s[col])   + lpbg;
                    float v1 = fmaf(-0.5f, c[u][j][2*h+1], offs_s[col+1]) + lpbg;
                    lp[2*j] = v0; lp[2*j+1] = v1;
                    mx = fmaxf(mx, fmaxf(v0 + lpi_s[col], v1 + lpi_s[col+1]));
                }
                mx = fmaxf(mx, __shfl_xor_sync(0xffffffffu, mx, 1));
                mx = fmaxf(mx, __shfl_xor_sync(0xffffffffu, mx, 2));
                float se = 0.f;
                #pragma unroll
                for (int j = 0; j < 8; j++) {
                    int col = 8 * j + 2 * t4;
                    se += __expf(lp[2*j]   + lpi_s[col]   - mx);
                    se += __expf(lp[2*j+1] + lpi_s[col+1] - mx);
                }
                se += __shfl_xor_sync(0xffffffffu, se, 1);
                se += __shfl_xor_sync(0xffffffffu, se, 2);
                if (t4 == 0) lsesum += (double)(mx + __logf(se));
                // direct stores (out+65 is 4B-aligned -> scalar STG.32)
                float* op = out + 65 + ((size_t)(n0 + r)) * Kk;
                #pragma unroll
                for (int j = 0; j < 8; j++) {
                    op[8*j + 2*t4]     = lp[2*j];
                    op[8*j + 2*t4 + 1] = lp[2*j+1];
                }
            }
        }
    }

    // ---- loss reduce + last-CTA finalize (and replay reset) ----
    #pragma unroll
    for (int s = 16; s; s >>= 1)
        lsesum += __shfl_xor_sync(0xffffffffu, lsesum, s);
    if (lane == 0) wsum[wid] = lsesum;
    __syncthreads();
    if (tid == 0) {
        double bsum = 0.0;
        #pragma unroll
        for (int w = 0; w < TPB / 32; w++) bsum += wsum[w];
        atomicAdd(&g_lse, bsum);
        __threadfence();
        unsigned int old = atomicAdd(&g_count, 1u);
        if (old == GRID - 1) {
            __threadfence();
            double total = atomicAdd(&g_lse, 0.0);
            out[0] = (float)((double)kl_s * (double)Nn - total);
            g_lse  = 0.0;
            g_tile = 0u;
            g_count = 0u;
        }
    }
}

// ---------------------------------------------------------------------------
extern "C" void kernel_launch(void* const* d_in, const int* in_sizes, int n_in,
                              void* d_out, int out_size)
{
    const float* X  = (const float*)d_in[0];
    const float* u  = (const float*)d_in[1];
    const float* pl = (const float*)d_in[2];
    const float* mu = (const float*)d_in[3];
    const float* lv = (const float*)d_in[4];
    const float* pi = (const float*)d_in[5];
    const float* pp = (const float*)d_in[6];
    float* out = (float*)d_out;

    cudaFuncSetAttribute(gmm_kernel,
                         cudaFuncAttributeMaxDynamicSharedMemorySize, SMEM_BYTES);

    gmm_kernel<<<GRID, TPB, SMEM_BYTES>>>(X, u, pl, mu, lv, pi, pp, out);
}

// round 8
// speedup vs baseline: 1.0871x; 1.0871x over previous
#include <cuda_runtime.h>
#include <cuda_fp16.h>
#include <math.h>
#include <stdint.h>

// ---------------- problem constants ----------------
#define Nn 262144
#define Dd 64
#define Kk 64
#define TPB 256
#define GRID 296                 // persistent CTAs (2/SM x 148)
#define NCHUNK (Nn/16)           // 16384 m16 chunks
#define WSTRIDE (GRID*8)         // 2368 warps
#define LOG2PI_F 1.83787706640934548356f
#define EXP2_F 7.389056098930650f    // exp(2) = exp(-prior_logvar_0)

// ---------------- device globals ----------------
__device__ double g_lse;
__device__ unsigned int g_count;

__device__ __forceinline__ void mma16(float c[4], const uint32_t a[4],
                                      uint32_t b0, uint32_t b1) {
    asm volatile("mma.sync.aligned.m16n8k16.row.col.f32.f16.f16.f32 "
        "{%0,%1,%2,%3},{%4,%5,%6,%7},{%8,%9},{%0,%1,%2,%3};"
        : "+f"(c[0]), "+f"(c[1]), "+f"(c[2]), "+f"(c[3])
        : "r"(a[0]), "r"(a[1]), "r"(a[2]), "r"(a[3]), "r"(b0), "r"(b1));
}
__device__ __forceinline__ uint32_t h2sq(uint32_t a) {
    __half2 h = *reinterpret_cast<__half2*>(&a);
    __half2 q = __hmul2(h, h);
    return *reinterpret_cast<uint32_t*>(&q);
}
__device__ __forceinline__ uint32_t f2h2(float lo, float hi) {
    __half2 h = __floats2half2_rn(lo, hi);
    return *reinterpret_cast<uint32_t*>(&h);
}

// ---------------------------------------------------------------------------
__global__ void __launch_bounds__(TPB, 2)
gmm_kernel(const float* __restrict__ X,
           const float* __restrict__ u_noise,
           const float* __restrict__ phi_logits,
           const float* __restrict__ q_mu,
           const float* __restrict__ q_logvar,
           const float* __restrict__ pi_logits,
           const float* __restrict__ prior_p,
           float* __restrict__ out)
{
    // static smem (~19 KB): B fragments + small vectors
    __shared__ float4 B_s[8 * 4 * 32];     // packed B frags (16 KB)
    __shared__ float  offs_s[64], lpi_s[64], wbg_s[64], phi_s[64];
    __shared__ float  scr[256];
    __shared__ float  kl_s, c0_s;
    __shared__ double wsum[TPB / 32];

    const int tid = threadIdx.x, wid = tid >> 5, lane = tid & 31;
    const int g = lane >> 2, t4 = lane & 3;

    // ---------------- in-CTA precompute ----------------
    if (tid < 64) {
        float uu  = u_noise[tid];
        float gmb = -__logf(-__logf(uu + 1e-9f) + 1e-9f);
        float pl  = phi_logits[tid];
        float phi = 1.0f / (1.0f + __expf(-(pl + gmb)));
        phi_s[tid] = phi;
        float qphi = 1.0f / (1.0f + __expf(-pl));
        qphi = fminf(fmaxf(qphi, 1e-6f), 1.0f - 1e-6f);
        if (blockIdx.x == 0) out[1 + tid] = qphi;
        float p = fminf(fmaxf(prior_p[tid], 1e-6f), 1.0f - 1e-6f);
        scr[tid]       = qphi * (__logf(qphi) - __logf(p))
                       + (1.0f - qphi) * (__logf(1.0f - qphi) - __logf(1.0f - p));
        scr[64 + tid]  = (1.0f - phi) * (LOG2PI_F - 2.0f);
        scr[128 + tid] = pi_logits[tid];
        wbg_s[tid]     = (1.0f - phi) * EXP2_F;
    }
    __syncthreads();
    if (tid == 0) {
        float kl = 0.f, c0 = 0.f;
        #pragma unroll
        for (int i = 0; i < 64; i++) { kl += scr[i]; c0 += scr[64 + i]; }
        kl_s = kl; c0_s = c0;
    }
    if (tid < 64) {     // log(softmax(pi)+1e-9)
        float m = -3.4e38f;
        #pragma unroll
        for (int k = 0; k < 64; k++) m = fmaxf(m, scr[128 + k]);
        float ss = 0.f;
        #pragma unroll
        for (int k = 0; k < 64; k++) ss += __expf(scr[128 + k] - m);
        lpi_s[tid] = __logf(__expf(scr[128 + tid] - m) / ss + 1e-9f);
    }

    // packed B fragments: entry e = (j*4 + ks)*32 + le
    // float4 = { h2(lin d0,d0+1), h2(lin d0+8,d0+9), h2(a d0,d0+1), h2(a d0+8,d0+9) }
    for (int e = tid; e < 8 * 4 * 32; e += TPB) {
        int le = e & 31, ks = (e >> 5) & 3, j = e >> 7;
        int n = 8 * j + (le >> 2);
        int d0 = 16 * ks + 2 * (le & 3);
        float lin[4], aa[4];
        #pragma unroll
        for (int p = 0; p < 4; p++) {
            int d = d0 + (p & 1) + (p >> 1) * 8;        // d0, d0+1, d0+8, d0+9
            float lv = fminf(fmaxf(q_logvar[n * Dd + d], -5.0f), 5.0f);
            float a  = phi_s[d] * __expf(-lv);
            aa[p]  = a;
            lin[p] = -2.0f * q_mu[n * Dd + d] * a;
        }
        float4 v;
        *(uint32_t*)&v.x = f2h2(lin[0], lin[1]);
        *(uint32_t*)&v.y = f2h2(lin[2], lin[3]);
        *(uint32_t*)&v.z = f2h2(aa[0],  aa[1]);
        *(uint32_t*)&v.w = f2h2(aa[2],  aa[3]);
        B_s[e] = v;
    }
    __syncthreads();    // scr free; reuse for offs partials
    {
        int k = tid & 63, part = tid >> 6;
        float s = 0.f;
        #pragma unroll
        for (int d = part * 16; d < part * 16 + 16; d++) {
            float lv = fminf(fmaxf(q_logvar[k * Dd + d], -5.0f), 5.0f);
            float a  = phi_s[d] * __expf(-lv);
            float mu = q_mu[k * Dd + d];
            s += phi_s[d] * (LOG2PI_F + lv) + mu * mu * a;
        }
        scr[tid] = s;
    }
    __syncthreads();
    if (tid < 64)
        offs_s[tid] = -0.5f * (scr[tid] + scr[64 + tid] + scr[128 + tid] + scr[192 + tid]);
    __syncthreads();    // LAST sync: B_s/offs_s/lpi_s/wbg_s read-only from here

    const float C0 = c0_s;
    const int gwarp = blockIdx.x * 8 + wid;
    double lsesum = 0.0;

    // hoisted background weights for this lane's columns (8 float2)
    float2 wq[4][2];
    #pragma unroll
    for (int ks = 0; ks < 4; ks++) {
        wq[ks][0] = *(const float2*)(wbg_s + 16 * ks + 2 * t4);
        wq[ks][1] = *(const float2*)(wbg_s + 16 * ks + 2 * t4 + 8);
    }

    // =================== independent per-warp chunk loop ===================
    for (int chunk = gwarp; chunk < NCHUNK; chunk += WSTRIDE) {
        const int row0 = chunk * 16;
        const float2* Xg = (const float2*)X + (size_t)(row0 + g) * 32 + t4;

        // ---- batched fragment loads (16 LDG.64, full MLP) ----
        float2 v[4][4];
        #pragma unroll
        for (int ks = 0; ks < 4; ks++) {
            v[ks][0] = Xg[8 * ks];             // row g,   cols 16ks+2t4..+1
            v[ks][1] = Xg[8 * 32 + 8 * ks];    // row g+8
            v[ks][2] = Xg[8 * ks + 4];         // row g,   cols +8
            v[ks][3] = Xg[8 * 32 + 8 * ks + 4];
        }

        // ---- convert to fp16 frags, square, exact fp32 bg partials ----
        uint32_t A[4][4], Q[4][4];
        float bg0 = 0.f, bg1 = 0.f;
        #pragma unroll
        for (int ks = 0; ks < 4; ks++) {
            #pragma unroll
            for (int p = 0; p < 4; p++) {
                A[ks][p] = f2h2(v[ks][p].x, v[ks][p].y);
                Q[ks][p] = h2sq(A[ks][p]);
            }
            bg0 = fmaf(wq[ks][0].x, v[ks][0].x * v[ks][0].x, bg0);
            bg0 = fmaf(wq[ks][0].y, v[ks][0].y * v[ks][0].y, bg0);
            bg0 = fmaf(wq[ks][1].x, v[ks][2].x * v[ks][2].x, bg0);
            bg0 = fmaf(wq[ks][1].y, v[ks][2].y * v[ks][2].y, bg0);
            bg1 = fmaf(wq[ks][0].x, v[ks][1].x * v[ks][1].x, bg1);
            bg1 = fmaf(wq[ks][0].y, v[ks][1].y * v[ks][1].y, bg1);
            bg1 = fmaf(wq[ks][1].x, v[ks][3].x * v[ks][3].x, bg1);
            bg1 = fmaf(wq[ks][1].y, v[ks][3].y * v[ks][3].y, bg1);
        }
        bg0 += __shfl_xor_sync(0xffffffffu, bg0, 1);
        bg0 += __shfl_xor_sync(0xffffffffu, bg0, 2);
        bg1 += __shfl_xor_sync(0xffffffffu, bg1, 1);
        bg1 += __shfl_xor_sync(0xffffffffu, bg1, 2);

        // ---- MMA: 4 ksteps x 8 n-tiles x (lin + quad) ----
        float c[8][4];
        #pragma unroll
        for (int j = 0; j < 8; j++)
            { c[j][0]=0.f; c[j][1]=0.f; c[j][2]=0.f; c[j][3]=0.f; }
        #pragma unroll
        for (int ks = 0; ks < 4; ks++) {
            const float4* bp = B_s + ks * 32 + lane;
            #pragma unroll
            for (int j = 0; j < 8; j++) {
                float4 b = bp[j * 128];
                mma16(c[j], A[ks], *(uint32_t*)&b.x, *(uint32_t*)&b.y);
                mma16(c[j], Q[ks], *(uint32_t*)&b.z, *(uint32_t*)&b.w);
            }
        }

        // ---- epilogue: rows g (h=0) and g+8 (h=1) ----
        #pragma unroll
        for (int h = 0; h < 2; h++) {
            float lpbg = -0.5f * (C0 + (h ? bg1 : bg0));
            float lp[16];
            float mx = -3.4e38f;
            #pragma unroll
            for (int j = 0; j < 8; j++) {
                int col = 8 * j + 2 * t4;
                float v0 = fmaf(-0.5f, c[j][2*h],   offs_s[col])   + lpbg;
                float v1 = fmaf(-0.5f, c[j][2*h+1], offs_s[col+1]) + lpbg;
                lp[2*j] = v0; lp[2*j+1] = v1;
                mx = fmaxf(mx, fmaxf(v0 + lpi_s[col], v1 + lpi_s[col+1]));
            }
            mx = fmaxf(mx, __shfl_xor_sync(0xffffffffu, mx, 1));
            mx = fmaxf(mx, __shfl_xor_sync(0xffffffffu, mx, 2));
            float se = 0.f;
            #pragma unroll
            for (int j = 0; j < 8; j++) {
                int col = 8 * j + 2 * t4;
                se += __expf(lp[2*j]   + lpi_s[col]   - mx);
                se += __expf(lp[2*j+1] + lpi_s[col+1] - mx);
            }
            se += __shfl_xor_sync(0xffffffffu, se, 1);
            se += __shfl_xor_sync(0xffffffffu, se, 2);
            if (t4 == 0) lsesum += (double)(mx + __logf(se));

            float* op = out + 65 + (size_t)(row0 + g + 8 * h) * Kk;
            #pragma unroll
            for (int j = 0; j < 8; j++) {
                op[8*j + 2*t4]     = lp[2*j];
                op[8*j + 2*t4 + 1] = lp[2*j+1];
            }
        }
    }

    // ---- loss reduce + last-CTA finalize (and deterministic replay reset) ----
    #pragma unroll
    for (int s = 16; s; s >>= 1)
        lsesum += __shfl_xor_sync(0xffffffffu, lsesum, s);
    if (lane == 0) wsum[wid] = lsesum;
    __syncthreads();
    if (tid == 0) {
        double bsum = 0.0;
        #pragma unroll
        for (int w = 0; w < TPB / 32; w++) bsum += wsum[w];
        atomicAdd(&g_lse, bsum);
        __threadfence();
        unsigned int old = atomicAdd(&g_count, 1u);
        if (old == GRID - 1) {
            __threadfence();
            double total = atomicAdd(&g_lse, 0.0);
            out[0] = (float)((double)kl_s * (double)Nn - total);
            g_lse   = 0.0;
            g_count = 0u;
        }
    }
}

// ---------------------------------------------------------------------------
extern "C" void kernel_launch(void* const* d_in, const int* in_sizes, int n_in,
                              void* d_out, int out_size)
{
    const float* X  = (const float*)d_in[0];
    const float* u  = (const float*)d_in[1];
    const float* pl = (const float*)d_in[2];
    const float* mu = (const float*)d_in[3];
    const float* lv = (const float*)d_in[4];
    const float* pi = (const float*)d_in[5];
    const float* pp = (const float*)d_in[6];
    float* out = (float*)d_out;

    gmm_kernel<<<GRID, TPB>>>(X, u, pl, mu, lv, pi, pp, out);
}